// round 6
// baseline (speedup 1.0000x reference)
#include <cuda_runtime.h>
#include <math.h>

#define BT      4096
#define KK      64
#define DD      256
#define PP      4
#define KPP     16
#define ROWS    16
#define TH2     512
#define WST     257

typedef unsigned long long ULL;

__device__ __align__(16) float u_scratch[(size_t)BT * 1024];

__device__ __forceinline__ void fma2(ULL &acc, ULL a, ULL b) {
    asm("fma.rn.f32x2 %0, %1, %2, %0;" : "+l"(acc) : "l"(a), "l"(b));
}
__device__ __forceinline__ ULL pack2(float lo, float hi) {
    ULL r; asm("mov.b64 %0, {%1, %2};" : "=l"(r) : "f"(lo), "f"(hi)); return r;
}
__device__ __forceinline__ void unpack2(ULL a, float &lo, float &hi) {
    asm("mov.b64 {%0, %1}, %2;" : "=f"(lo), "=f"(hi) : "l"(a));
}
__device__ __forceinline__ ULL mul2(ULL a, ULL b) {
    ULL r; asm("mul.rn.f32x2 %0, %1, %2;" : "=l"(r) : "l"(a), "l"(b)); return r;
}
__device__ __forceinline__ ULL add2(ULL a, ULL b) {
    ULL r; asm("add.rn.f32x2 %0, %1, %2;" : "=l"(r) : "l"(a), "l"(b)); return r;
}

// ===================== Kernel A: weighted segment-sum (HBM stream) ==========
__global__ __launch_bounds__(256)
void fs_phase1(const float* __restrict__ E_S, const float* __restrict__ W,
               const int* __restrict__ part_idx)
{
    __shared__ float w_s[2 * KK];
    __shared__ float winv_s[2 * PP];
    __shared__ int   pidx_s[KK];

    const int tid = threadIdx.x;
    const int bx  = blockIdx.x;
    const int row0 = bx * 2;

    if (tid < KK)  pidx_s[tid] = part_idx[tid];
    if (tid < 2 * KK) w_s[tid] = W[(size_t)row0 * KK + tid];
    __syncthreads();
    if (tid < 2 * PP) {
        int r = tid >> 2, p = tid & 3;
        float s = 0.f;
#pragma unroll
        for (int kp = 0; kp < KPP; kp++) s += w_s[r * KK + pidx_s[p * KPP + kp]];
        winv_s[tid] = 1.0f / (s + 1e-6f);
    }
    __syncthreads();

    const int p0 = tid >> 6;
    const int d4 = tid & 63;
    const float4* Ea = (const float4*)(E_S + (size_t)row0 * KK * DD);
    const float4* Eb = Ea + (KK * DD / 4);

    float4 aa = make_float4(0.f,0.f,0.f,0.f);
    float4 ab = make_float4(0.f,0.f,0.f,0.f);
#pragma unroll
    for (int kp = 0; kp < KPP; kp++) {
        const int k  = pidx_s[p0 * KPP + kp];
        const float wa = w_s[k];
        const float wb = w_s[KK + k];
        const float4 ea = Ea[k * 64 + d4];
        const float4 eb = Eb[k * 64 + d4];
        aa.x = fmaf(wa, ea.x, aa.x); aa.y = fmaf(wa, ea.y, aa.y);
        aa.z = fmaf(wa, ea.z, aa.z); aa.w = fmaf(wa, ea.w, aa.w);
        ab.x = fmaf(wb, eb.x, ab.x); ab.y = fmaf(wb, eb.y, ab.y);
        ab.z = fmaf(wb, eb.z, ab.z); ab.w = fmaf(wb, eb.w, ab.w);
    }
    const float iva = winv_s[p0];
    const float ivb = winv_s[PP + p0];

    float4 s0 = make_float4(aa.x * iva, ab.x * ivb, aa.y * iva, ab.y * ivb);
    float4 s1 = make_float4(aa.z * iva, ab.z * ivb, aa.w * iva, ab.w * ivb);

    const size_t group = bx >> 3;
    const int    r2g   = bx & 7;
    float4* out4 = ((float4*)u_scratch) + group * 4096 + (size_t)(p0 * 8 + r2g) * 128 + d4 * 2;
    out4[0] = s0;
    out4[1] = s1;
}

// ===================== Kernel B: 512-thr double-buffered FFMA2 GEMM =========
// smem: u[8192] ULL | red[8192] ULL | wt0/wt1[32*257] f | alpha[64] f | redf[256] f
#define SMEMB_BYTES (8192*8 + 8192*8 + 2*32*WST*4 + 64*4 + 256*4)

// tile T: 0..31 = part_W (p=T>>3, k-chunk T&7), 32..63 = proj_W (k-chunk T-32)
__device__ __forceinline__ void ldg_tile(float4 pf[4], int T,
                                         const float* __restrict__ pw,
                                         const float* __restrict__ qw,
                                         int w, int lane) {
    const float* base; int rstride, off0;
    if (T < 32) { base = pw + (size_t)(T >> 3) * (DD * DD); rstride = DD;   off0 = (T & 7) * 32; }
    else        { base = qw;                                 rstride = 1024; off0 = (T - 32) * 32; }
    const int koff = (lane & 7) * 4;
    const int osub = w * 4 + (lane >> 3);        // 0..63
#pragma unroll
    for (int it = 0; it < 4; it++) {
        const int o = it * 64 + osub;
        pf[it] = *(const float4*)(base + (size_t)o * rstride + off0 + koff);
    }
}
__device__ __forceinline__ void sts_tile(float* wt, const float4 pf[4], int w, int lane) {
    const int koff = (lane & 7) * 4;
    const int osub = w * 4 + (lane >> 3);
#pragma unroll
    for (int it = 0; it < 4; it++) {
        const int o = it * 64 + osub;
        wt[(koff + 0) * WST + o] = pf[it].x;
        wt[(koff + 1) * WST + o] = pf[it].y;
        wt[(koff + 2) * WST + o] = pf[it].z;
        wt[(koff + 3) * WST + o] = pf[it].w;
    }
}
// warp tile: 4 rowpairs (rg) x 4 col-chunks (cg half, lane+32cc), K-slice ks*8..+8
__device__ __forceinline__ void compute_tile(ULL acc[4][4], const ULL* ub,
                                             const float* wt, int ks, int cg, int lane) {
#pragma unroll
    for (int k2 = 0; k2 < 4; k2++) {
        const int kl = ks * 8 + 2 * k2;
        ulonglong2 uv[4];
#pragma unroll
        for (int rp = 0; rp < 4; rp++) uv[rp] = *(const ulonglong2*)(ub + rp * 256 + kl);
        const float* w0p = wt + kl * WST + cg * 128 + lane;
        const float* w1p = w0p + WST;
#pragma unroll
        for (int cc = 0; cc < 4; cc++) {
            const float a0 = w0p[cc * 32], a1 = w1p[cc * 32];
            const ULL W0 = pack2(a0, a0);
            const ULL W1 = pack2(a1, a1);
#pragma unroll
            for (int rp = 0; rp < 4; rp++) {
                fma2(acc[rp][cc], uv[rp].x, W0);
                fma2(acc[rp][cc], uv[rp].y, W1);
            }
        }
    }
}

__global__ __launch_bounds__(TH2, 1)
void fs_phase2(const float* __restrict__ part_W, const float* __restrict__ part_b,
               const float* __restrict__ v, const float* __restrict__ c,
               const float* __restrict__ ln_g, const float* __restrict__ ln_b,
               const float* __restrict__ proj_W, const float* __restrict__ proj_b,
               const float* __restrict__ out_g, const float* __restrict__ out_b,
               float* __restrict__ out)
{
    extern __shared__ char smraw[];
    ULL*   u       = (ULL*)smraw;                  // [4p][8rp][256]
    ULL*   red     = u + 8192;                     // [4ks][8rp][256]
    float* wt0     = (float*)(red + 8192);         // [32][WST]
    float* wt1     = wt0 + 32 * WST;
    float* alpha_s = wt1 + 32 * WST;               // [64]
    float* redf    = alpha_s + 64;                 // [16][8][2]

    const int tid  = threadIdx.x;
    const int w    = tid >> 5, lane = tid & 31;
    const int ks   = w & 3;            // K-split quarter
    const int rg   = (w >> 2) & 1;     // rowpair half
    const int cg   = w >> 3;           // column half
    const int bt0  = blockIdx.x * ROWS;
    const int colhi = tid >> 8;        // 0/1 (for 512-thread epilogues)
    const int col   = tid & 255;

    // stage u tile (L2-hot, packed row-pairs [p][rp][i])
    {
        const float4* gsrc = ((const float4*)u_scratch) + (size_t)blockIdx.x * 4096;
        float4* u4 = (float4*)u;
#pragma unroll
        for (int n = 0; n < 8; n++) u4[tid + n * TH2] = gsrc[tid + n * TH2];
    }

    float4 pf[4];
    ldg_tile(pf, 0, part_W, proj_W, w, lane);
    __syncthreads();                 // u ready
    sts_tile(wt0, pf, w, lane);
    __syncthreads();                 // wt0 ready

    float* wbuf[2] = { wt0, wt1 };

    ULL acc[4][4];
#pragma unroll
    for (int rp = 0; rp < 4; rp++)
#pragma unroll
        for (int cc = 0; cc < 4; cc++) acc[rp][cc] = 0ull;

#pragma unroll 1
    for (int T = 0; T < 64; T++) {
        if (T < 63) ldg_tile(pf, T + 1, part_W, proj_W, w, lane);

        const int Tl = (T < 32) ? T : T - 32;
        const ULL* ub = u + ((Tl >> 3) * 8 + rg * 4) * 256 + (Tl & 7) * 32;
        compute_tile(acc, ub, wbuf[T & 1], ks, cg, lane);

        const bool boundary = ((T < 32) && ((T & 7) == 7)) || (T == 63);
        if (boundary) {
            // write K-split partials, reset accumulators
#pragma unroll
            for (int rp = 0; rp < 4; rp++) {
                ULL* dst = red + ks * 2048 + (rg * 4 + rp) * 256 + cg * 128 + lane;
#pragma unroll
                for (int cc = 0; cc < 4; cc++) { dst[cc * 32] = acc[rp][cc]; acc[rp][cc] = 0ull; }
            }
        }
        if (T < 63) sts_tile(wbuf[(T + 1) & 1], pf, w, lane);
        __syncthreads();

        if (boundary) {
            if (T < 32) {
                const int p = T >> 3;
#pragma unroll
                for (int j = 0; j < 4; j++) {
                    const int idx = tid + j * TH2;
                    const float b = part_b[p * DD + (idx & 255)];
                    ULL s = add2(add2(red[idx], red[2048 + idx]),
                                 add2(red[4096 + idx], red[6144 + idx]));
                    u[p * 2048 + idx] = add2(s, pack2(b, b));
                }
            } else {
#pragma unroll
                for (int j = 0; j < 4; j++) {
                    const int idx = tid + j * TH2;
                    const float b = proj_b[idx & 255];
                    ULL s = add2(add2(red[idx], red[2048 + idx]),
                                 add2(red[4096 + idx], red[6144 + idx]));
                    red[idx] = add2(s, pack2(b, b));
                }
            }
            __syncthreads();

            if (T == 31) {
                // LN stats + sigmoid gate: 64 (row,part) pairs, 4 per warp
                const float* uh = (const float*)u;
#pragma unroll 1
                for (int j = 0; j < 4; j++) {
                    const int pair = w * 4 + j;
                    const int r = pair >> 2, p = pair & 3;
                    const int base = ((p * 8 + (r >> 1)) * 256) * 2 + (r & 1);
                    float s1 = 0.f, s2 = 0.f, s3 = 0.f, s4 = 0.f, s5 = 0.f;
#pragma unroll
                    for (int i = 0; i < DD / 32; i++) {
                        const int cl = lane + i * 32;
                        const float x  = uh[base + cl * 2];
                        const float vv = v[p * DD + cl];
                        const float gv = ln_g[p * DD + cl] * vv;
                        const float bv = ln_b[p * DD + cl] * vv;
                        s1 += x; s2 += x * x; s3 += x * gv; s4 += gv; s5 += bv;
                    }
#pragma unroll
                    for (int off = 16; off; off >>= 1) {
                        s1 += __shfl_xor_sync(0xffffffffu, s1, off);
                        s2 += __shfl_xor_sync(0xffffffffu, s2, off);
                        s3 += __shfl_xor_sync(0xffffffffu, s3, off);
                        s4 += __shfl_xor_sync(0xffffffffu, s4, off);
                        s5 += __shfl_xor_sync(0xffffffffu, s5, off);
                    }
                    if (lane == 0) {
                        const float m   = s1 * (1.0f / DD);
                        const float var = s2 * (1.0f / DD) - m * m;
                        const float rs  = rsqrtf(var + 1e-5f);
                        const float dot = rs * (s3 - m * s4) + s5 + c[p];
                        alpha_s[r * PP + p] = 1.0f / (1.0f + __expf(-dot));
                    }
                }
                __syncthreads();
                // scale u_hat by alpha -> Z
#pragma unroll
                for (int p = 0; p < PP; p++)
#pragma unroll
                    for (int r2l = 0; r2l < 4; r2l++) {
                        const int r2 = colhi * 4 + r2l;
                        const ULL ap = pack2(alpha_s[(2 * r2) * PP + p],
                                             alpha_s[(2 * r2 + 1) * PP + p]);
                        const int idx = (p * 8 + r2) * 256 + col;
                        u[idx] = mul2(u[idx], ap);
                    }
                __syncthreads();
            }
        }
    }

    // ---- final LayerNorm across D (S in red[rp*256+col]); half-rows per tid ----
    {
        float x[8];
#pragma unroll
        for (int r2l = 0; r2l < 4; r2l++)
            unpack2(red[(colhi * 4 + r2l) * 256 + col], x[2 * r2l], x[2 * r2l + 1]);

        const int wloc = w & 7;   // warp index within its col-half group
#pragma unroll
        for (int rl = 0; rl < 8; rl++) {
            float s1 = x[rl];
            float s2 = x[rl] * x[rl];
#pragma unroll
            for (int off = 16; off; off >>= 1) {
                s1 += __shfl_xor_sync(0xffffffffu, s1, off);
                s2 += __shfl_xor_sync(0xffffffffu, s2, off);
            }
            if (lane == 0) {
                const int r = colhi * 8 + rl;
                redf[(r * 8 + wloc) * 2 + 0] = s1;
                redf[(r * 8 + wloc) * 2 + 1] = s2;
            }
        }
        __syncthreads();
        const float og = out_g[col], ob = out_b[col];
#pragma unroll
        for (int rl = 0; rl < 8; rl++) {
            const int r = colhi * 8 + rl;
            float s1 = 0.f, s2 = 0.f;
#pragma unroll
            for (int ww = 0; ww < 8; ww++) {
                s1 += redf[(r * 8 + ww) * 2 + 0];
                s2 += redf[(r * 8 + ww) * 2 + 1];
            }
            const float m   = s1 * (1.0f / DD);
            const float var = s2 * (1.0f / DD) - m * m;
            const float rs  = rsqrtf(var + 1e-5f);
            out[(size_t)(bt0 + r) * DD + col] = (x[rl] - m) * rs * og + ob;
        }
    }
}

extern "C" void kernel_launch(void* const* d_in, const int* in_sizes, int n_in,
                              void* d_out, int out_size)
{
    (void)in_sizes; (void)n_in; (void)out_size;
    const float* E_S    = (const float*)d_in[0];
    const float* W      = (const float*)d_in[1];
    const int*   pidx   = (const int*)  d_in[2];
    const float* part_W = (const float*)d_in[3];
    const float* part_b = (const float*)d_in[4];
    const float* v      = (const float*)d_in[5];
    const float* c      = (const float*)d_in[6];
    const float* ln_g   = (const float*)d_in[7];
    const float* ln_b   = (const float*)d_in[8];
    const float* proj_W = (const float*)d_in[9];
    const float* proj_b = (const float*)d_in[10];
    const float* out_g  = (const float*)d_in[11];
    const float* out_b  = (const float*)d_in[12];
    float* out = (float*)d_out;

    fs_phase1<<<BT / 2, 256>>>(E_S, W, pidx);

    cudaFuncSetAttribute(fs_phase2, cudaFuncAttributeMaxDynamicSharedMemorySize, SMEMB_BYTES);
    fs_phase2<<<BT / ROWS, TH2, SMEMB_BYTES>>>(
        part_W, part_b, v, c, ln_g, ln_b,
        proj_W, proj_b, out_g, out_b, out);
}

// round 7
// speedup vs baseline: 1.2127x; 1.2127x over previous
#include <cuda_runtime.h>
#include <math.h>

#define BT      4096
#define KK      64
#define DD      256
#define PP      4
#define KPP     16
#define ROWS    16
#define THREADS 256
#define WST     257

typedef unsigned long long ULL;

__device__ __align__(16) float u_scratch[(size_t)BT * 1024];

__device__ __forceinline__ void fma2(ULL &acc, ULL a, ULL b) {
    asm("fma.rn.f32x2 %0, %1, %2, %0;" : "+l"(acc) : "l"(a), "l"(b));
}
__device__ __forceinline__ ULL pack2(float lo, float hi) {
    ULL r; asm("mov.b64 %0, {%1, %2};" : "=l"(r) : "f"(lo), "f"(hi)); return r;
}
__device__ __forceinline__ void unpack2(ULL a, float &lo, float &hi) {
    asm("mov.b64 {%0, %1}, %2;" : "=f"(lo), "=f"(hi) : "l"(a));
}
__device__ __forceinline__ ULL mul2(ULL a, ULL b) {
    ULL r; asm("mul.rn.f32x2 %0, %1, %2;" : "=l"(r) : "l"(a), "l"(b)); return r;
}
__device__ __forceinline__ ULL add2(ULL a, ULL b) {
    ULL r; asm("add.rn.f32x2 %0, %1, %2;" : "=l"(r) : "l"(a), "l"(b)); return r;
}

// ===================== Kernel A: weighted segment-sum (HBM stream) ==========
__global__ __launch_bounds__(256)
void fs_phase1(const float* __restrict__ E_S, const float* __restrict__ W,
               const int* __restrict__ part_idx)
{
    __shared__ float w_s[2 * KK];
    __shared__ float winv_s[2 * PP];
    __shared__ int   pidx_s[KK];

    const int tid = threadIdx.x;
    const int bx  = blockIdx.x;
    const int row0 = bx * 2;

    if (tid < KK)  pidx_s[tid] = part_idx[tid];
    if (tid < 2 * KK) w_s[tid] = W[(size_t)row0 * KK + tid];
    __syncthreads();
    if (tid < 2 * PP) {
        int r = tid >> 2, p = tid & 3;
        float s = 0.f;
#pragma unroll
        for (int kp = 0; kp < KPP; kp++) s += w_s[r * KK + pidx_s[p * KPP + kp]];
        winv_s[tid] = 1.0f / (s + 1e-6f);
    }
    __syncthreads();

    const int p0 = tid >> 6;
    const int d4 = tid & 63;
    const float4* Ea = (const float4*)(E_S + (size_t)row0 * KK * DD);
    const float4* Eb = Ea + (KK * DD / 4);

    float4 aa = make_float4(0.f,0.f,0.f,0.f);
    float4 ab = make_float4(0.f,0.f,0.f,0.f);
#pragma unroll
    for (int kp = 0; kp < KPP; kp++) {
        const int k  = pidx_s[p0 * KPP + kp];
        const float wa = w_s[k];
        const float wb = w_s[KK + k];
        const float4 ea = Ea[k * 64 + d4];
        const float4 eb = Eb[k * 64 + d4];
        aa.x = fmaf(wa, ea.x, aa.x); aa.y = fmaf(wa, ea.y, aa.y);
        aa.z = fmaf(wa, ea.z, aa.z); aa.w = fmaf(wa, ea.w, aa.w);
        ab.x = fmaf(wb, eb.x, ab.x); ab.y = fmaf(wb, eb.y, ab.y);
        ab.z = fmaf(wb, eb.z, ab.z); ab.w = fmaf(wb, eb.w, ab.w);
    }
    const float iva = winv_s[p0];
    const float ivb = winv_s[PP + p0];

    float4 s0 = make_float4(aa.x * iva, ab.x * ivb, aa.y * iva, ab.y * ivb);
    float4 s1 = make_float4(aa.z * iva, ab.z * ivb, aa.w * iva, ab.w * ivb);

    const size_t group = bx >> 3;
    const int    r2g   = bx & 7;
    float4* out4 = ((float4*)u_scratch) + group * 4096 + (size_t)(p0 * 8 + r2g) * 128 + d4 * 2;
    out4[0] = s0;
    out4[1] = s1;
}

// ===================== Kernel B: 2-CTA/SM FFMA2 GEMM, no red buffer =========
// smem: u[8192] ULL (64KB) | wt[32*257] f (~33KB, reused as S at end) |
//       alpha[64] f | redf[256] f   => ~98.4 KB -> 2 CTAs/SM
#define SMEMB_BYTES (8192*8 + 32*WST*4 + 64*4 + 256*4)

// tile T: 0..31 = part_W (p=T>>3, k-chunk T&7), 32..63 = proj_W (k-chunk T-32)
__device__ __forceinline__ void ldg_tile(float4 pf[8], int T,
                                         const float* __restrict__ pw,
                                         const float* __restrict__ qw,
                                         int w, int lane) {
    const float* base; int rstride, off0;
    if (T < 32) { base = pw + (size_t)(T >> 3) * (DD * DD); rstride = DD;   off0 = (T & 7) * 32; }
    else        { base = qw;                                 rstride = 1024; off0 = (T - 32) * 32; }
    const int koff = (lane & 7) * 4;
    const int osub = w * 4 + (lane >> 3);
#pragma unroll
    for (int it = 0; it < 8; it++) {
        const int o = it * 32 + osub;
        pf[it] = *(const float4*)(base + (size_t)o * rstride + off0 + koff);
    }
}
__device__ __forceinline__ void sts_tile(float* wt, const float4 pf[8], int w, int lane) {
    const int koff = (lane & 7) * 4;
    const int osub = w * 4 + (lane >> 3);
#pragma unroll
    for (int it = 0; it < 8; it++) {
        const int o = it * 32 + osub;
        wt[(koff + 0) * WST + o] = pf[it].x;
        wt[(koff + 1) * WST + o] = pf[it].y;
        wt[(koff + 2) * WST + o] = pf[it].z;
        wt[(koff + 3) * WST + o] = pf[it].w;
    }
}
// warp tile: 4 rowpairs (rg half) x 4 col-chunks (cg*128 + lane + 32cc), K-half ks
__device__ __forceinline__ void compute_tile(ULL acc[4][4], const ULL* ub,
                                             const float* wt, int ks, int cg, int lane) {
#pragma unroll
    for (int k2 = 0; k2 < 8; k2++) {
        const int kl = ks * 16 + 2 * k2;
        ulonglong2 uv[4];
#pragma unroll
        for (int rp = 0; rp < 4; rp++) uv[rp] = *(const ulonglong2*)(ub + rp * 256 + kl);
        const float* w0p = wt + kl * WST + cg * 128 + lane;
        const float* w1p = w0p + WST;
#pragma unroll
        for (int cc = 0; cc < 4; cc++) {
            const float a0 = w0p[cc * 32], a1 = w1p[cc * 32];
            const ULL W0 = pack2(a0, a0);
            const ULL W1 = pack2(a1, a1);
#pragma unroll
            for (int rp = 0; rp < 4; rp++) {
                fma2(acc[rp][cc], uv[rp].x, W0);
                fma2(acc[rp][cc], uv[rp].y, W1);
            }
        }
    }
}

__global__ __launch_bounds__(THREADS, 2)
void fs_phase2(const float* __restrict__ part_W, const float* __restrict__ part_b,
               const float* __restrict__ v, const float* __restrict__ c,
               const float* __restrict__ ln_g, const float* __restrict__ ln_b,
               const float* __restrict__ proj_W, const float* __restrict__ proj_b,
               const float* __restrict__ out_g, const float* __restrict__ out_b,
               float* __restrict__ out)
{
    extern __shared__ char smraw[];
    ULL*   u       = (ULL*)smraw;                  // [4p][8rp][256]
    float* wt      = (float*)(u + 8192);           // [32][WST]; reused as S at end
    float* alpha_s = wt + 32 * WST;                // [64]
    float* redf    = alpha_s + 64;                 // [16][8][2]
    ULL*   S_s     = (ULL*)wt;                     // [8rp][256] after last tile

    const int tid  = threadIdx.x;
    const int w    = tid >> 5, lane = tid & 31;
    const int rg   = w & 1;            // rowpair half
    const int cg   = (w >> 1) & 1;     // column half
    const int ks   = w >> 2;           // K half
    const int bt0  = blockIdx.x * ROWS;

    // stage u tile (L2-hot, packed row-pairs [p][rp][i])
    {
        const float4* gsrc = ((const float4*)u_scratch) + (size_t)blockIdx.x * 4096;
        float4* u4 = (float4*)u;
#pragma unroll
        for (int n = 0; n < 16; n++) u4[tid + n * THREADS] = gsrc[tid + n * THREADS];
    }

    float4 pf[8];
    ldg_tile(pf, 0, part_W, proj_W, w, lane);
    __syncthreads();                 // u ready
    sts_tile(wt, pf, w, lane);
    __syncthreads();                 // wt(0) ready

    ULL acc[4][4];
#pragma unroll
    for (int rp = 0; rp < 4; rp++)
#pragma unroll
        for (int cc = 0; cc < 4; cc++) acc[rp][cc] = 0ull;

#pragma unroll 1
    for (int T = 0; T < 64; T++) {
        if (T < 63) ldg_tile(pf, T + 1, part_W, proj_W, w, lane);

        const int Tl = (T < 32) ? T : T - 32;
        const ULL* ub = u + ((Tl >> 3) * 8 + rg * 4) * 256 + (Tl & 7) * 32;
        compute_tile(acc, ub, wt, ks, cg, lane);
        __syncthreads();             // compute done; wt free, u stable

        const bool bnd = ((T < 32) && ((T & 7) == 7)) || (T == 63);
        if (bnd) {
            if (T < 32) {
                const int p = T >> 3;
                // ks0 writes acc + bias; sync; ks1 adds (staggered, no red buffer)
                if (ks == 0) {
#pragma unroll
                    for (int rp = 0; rp < 4; rp++) {
                        ULL* dst = u + (p * 8 + rg * 4 + rp) * 256 + cg * 128 + lane;
#pragma unroll
                        for (int cc = 0; cc < 4; cc++) {
                            const float b = part_b[p * DD + cg * 128 + lane + cc * 32];
                            dst[cc * 32] = add2(acc[rp][cc], pack2(b, b));
                            acc[rp][cc] = 0ull;
                        }
                    }
                }
                __syncthreads();
                if (ks == 1) {
#pragma unroll
                    for (int rp = 0; rp < 4; rp++) {
                        ULL* dst = u + (p * 8 + rg * 4 + rp) * 256 + cg * 128 + lane;
#pragma unroll
                        for (int cc = 0; cc < 4; cc++) {
                            dst[cc * 32] = add2(dst[cc * 32], acc[rp][cc]);
                            acc[rp][cc] = 0ull;
                        }
                    }
                }
                __syncthreads();
            } else {
                // T==63: S into wt area
                if (ks == 0) {
#pragma unroll
                    for (int rp = 0; rp < 4; rp++) {
                        ULL* dst = S_s + (rg * 4 + rp) * 256 + cg * 128 + lane;
#pragma unroll
                        for (int cc = 0; cc < 4; cc++) {
                            const float b = proj_b[cg * 128 + lane + cc * 32];
                            dst[cc * 32] = add2(acc[rp][cc], pack2(b, b));
                        }
                    }
                }
                __syncthreads();
                if (ks == 1) {
#pragma unroll
                    for (int rp = 0; rp < 4; rp++) {
                        ULL* dst = S_s + (rg * 4 + rp) * 256 + cg * 128 + lane;
#pragma unroll
                        for (int cc = 0; cc < 4; cc++)
                            dst[cc * 32] = add2(dst[cc * 32], acc[rp][cc]);
                    }
                }
                __syncthreads();
            }

            if (T == 31) {
                // LN stats + sigmoid gate: 64 (row,part) pairs, 8 per warp
                const float* uh = (const float*)u;
#pragma unroll 1
                for (int j = 0; j < 8; j++) {
                    const int pair = w * 8 + j;
                    const int r = pair >> 2, p = pair & 3;
                    const int base = ((p * 8 + (r >> 1)) * 256) * 2 + (r & 1);
                    float s1 = 0.f, s2 = 0.f, s3 = 0.f, s4 = 0.f, s5 = 0.f;
#pragma unroll
                    for (int i = 0; i < DD / 32; i++) {
                        const int cl = lane + i * 32;
                        const float x  = uh[base + cl * 2];
                        const float vv = v[p * DD + cl];
                        const float gv = ln_g[p * DD + cl] * vv;
                        const float bv = ln_b[p * DD + cl] * vv;
                        s1 += x; s2 += x * x; s3 += x * gv; s4 += gv; s5 += bv;
                    }
#pragma unroll
                    for (int off = 16; off; off >>= 1) {
                        s1 += __shfl_xor_sync(0xffffffffu, s1, off);
                        s2 += __shfl_xor_sync(0xffffffffu, s2, off);
                        s3 += __shfl_xor_sync(0xffffffffu, s3, off);
                        s4 += __shfl_xor_sync(0xffffffffu, s4, off);
                        s5 += __shfl_xor_sync(0xffffffffu, s5, off);
                    }
                    if (lane == 0) {
                        const float m   = s1 * (1.0f / DD);
                        const float var = s2 * (1.0f / DD) - m * m;
                        const float rs  = rsqrtf(var + 1e-5f);
                        const float dot = rs * (s3 - m * s4) + s5 + c[p];
                        alpha_s[r * PP + p] = 1.0f / (1.0f + __expf(-dot));
                    }
                }
                __syncthreads();
                // scale u_hat by alpha -> Z
#pragma unroll
                for (int p = 0; p < PP; p++)
#pragma unroll
                    for (int r2 = 0; r2 < 8; r2++) {
                        const ULL ap = pack2(alpha_s[(2 * r2) * PP + p],
                                             alpha_s[(2 * r2 + 1) * PP + p]);
                        const int idx = (p * 8 + r2) * 256 + tid;
                        u[idx] = mul2(u[idx], ap);
                    }
                __syncthreads();
            }
        }

        if (T < 63) {
            sts_tile(wt, pf, w, lane);
            __syncthreads();          // wt(T+1) ready
        }
    }

    // ---- final LayerNorm across D (S in S_s[rp*256+col]) ----
    {
        float x[ROWS];
#pragma unroll
        for (int r2 = 0; r2 < 8; r2++) unpack2(S_s[r2 * 256 + tid], x[2 * r2], x[2 * r2 + 1]);

#pragma unroll
        for (int r = 0; r < ROWS; r++) {
            float s1 = x[r];
            float s2 = x[r] * x[r];
#pragma unroll
            for (int off = 16; off; off >>= 1) {
                s1 += __shfl_xor_sync(0xffffffffu, s1, off);
                s2 += __shfl_xor_sync(0xffffffffu, s2, off);
            }
            if (lane == 0) {
                redf[(r * 8 + w) * 2 + 0] = s1;
                redf[(r * 8 + w) * 2 + 1] = s2;
            }
        }
        __syncthreads();
        const float og = out_g[tid], ob = out_b[tid];
#pragma unroll
        for (int r = 0; r < ROWS; r++) {
            float s1 = 0.f, s2 = 0.f;
#pragma unroll
            for (int ww = 0; ww < 8; ww++) {
                s1 += redf[(r * 8 + ww) * 2 + 0];
                s2 += redf[(r * 8 + ww) * 2 + 1];
            }
            const float m   = s1 * (1.0f / DD);
            const float var = s2 * (1.0f / DD) - m * m;
            const float rs  = rsqrtf(var + 1e-5f);
            out[(size_t)(bt0 + r) * DD + tid] = (x[r] - m) * rs * og + ob;
        }
    }
}

extern "C" void kernel_launch(void* const* d_in, const int* in_sizes, int n_in,
                              void* d_out, int out_size)
{
    (void)in_sizes; (void)n_in; (void)out_size;
    const float* E_S    = (const float*)d_in[0];
    const float* W      = (const float*)d_in[1];
    const int*   pidx   = (const int*)  d_in[2];
    const float* part_W = (const float*)d_in[3];
    const float* part_b = (const float*)d_in[4];
    const float* v      = (const float*)d_in[5];
    const float* c      = (const float*)d_in[6];
    const float* ln_g   = (const float*)d_in[7];
    const float* ln_b   = (const float*)d_in[8];
    const float* proj_W = (const float*)d_in[9];
    const float* proj_b = (const float*)d_in[10];
    const float* out_g  = (const float*)d_in[11];
    const float* out_b  = (const float*)d_in[12];
    float* out = (float*)d_out;

    fs_phase1<<<BT / 2, 256>>>(E_S, W, pidx);

    cudaFuncSetAttribute(fs_phase2, cudaFuncAttributeMaxDynamicSharedMemorySize, SMEMB_BYTES);
    fs_phase2<<<BT / ROWS, THREADS, SMEMB_BYTES>>>(
        part_W, part_b, v, c, ln_g, ln_b,
        proj_W, proj_b, out_g, out_b, out);
}

// round 8
// speedup vs baseline: 1.2377x; 1.0206x over previous
#include <cuda_runtime.h>
#include <math.h>

#define BT   4096
#define KK   64
#define DD   256
#define PP   4
#define KPP  16

typedef unsigned long long ULL;

// scratch (device globals; no allocation)
__device__ __align__(16) float u_g[(size_t)BT * 1024];   // u  [4096][1024]
__device__ __align__(16) float h_g[(size_t)BT * 1024];   // u_hat -> Z (in place)
__device__ __align__(16) float s4_g[(size_t)4 * BT * 256]; // G2 K-split partials
__device__ __align__(16) float gv_g[1024];                // ln_g * v
__device__ float cst_g[8];                                // [p]=sum(gv), [4+p]=sum(ln_b*v)+c

__device__ __forceinline__ void fma2(ULL &acc, ULL a, ULL b) {
    asm("fma.rn.f32x2 %0, %1, %2, %0;" : "+l"(acc) : "l"(a), "l"(b));
}
__device__ __forceinline__ ULL pack2(float lo, float hi) {
    ULL r; asm("mov.b64 %0, {%1, %2};" : "=l"(r) : "f"(lo), "f"(hi)); return r;
}
__device__ __forceinline__ void unpack2(ULL a, float &lo, float &hi) {
    asm("mov.b64 {%0, %1}, %2;" : "=f"(lo), "=f"(hi) : "l"(a));
}
__device__ __forceinline__ ULL add2(ULL a, ULL b) {
    ULL r; asm("add.rn.f32x2 %0, %1, %2;" : "=l"(r) : "l"(a), "l"(b)); return r;
}

// ===================== K1: weighted segment-sum -> u_g (row-major) ==========
__global__ __launch_bounds__(256)
void k_seg(const float* __restrict__ E_S, const float* __restrict__ W,
           const int* __restrict__ part_idx)
{
    __shared__ float w_s[2 * KK];
    __shared__ float winv_s[2 * PP];
    __shared__ int   pidx_s[KK];

    const int tid = threadIdx.x;
    const int bx  = blockIdx.x;
    const int row0 = bx * 2;

    if (tid < KK)  pidx_s[tid] = part_idx[tid];
    if (tid < 2 * KK) w_s[tid] = W[(size_t)row0 * KK + tid];
    __syncthreads();
    if (tid < 2 * PP) {
        int r = tid >> 2, p = tid & 3;
        float s = 0.f;
#pragma unroll
        for (int kp = 0; kp < KPP; kp++) s += w_s[r * KK + pidx_s[p * KPP + kp]];
        winv_s[tid] = 1.0f / (s + 1e-6f);
    }
    __syncthreads();

    const int p0 = tid >> 6;
    const int d4 = tid & 63;
    const float4* Ea = (const float4*)(E_S + (size_t)row0 * KK * DD);
    const float4* Eb = Ea + (KK * DD / 4);

    float4 aa = make_float4(0.f,0.f,0.f,0.f);
    float4 ab = make_float4(0.f,0.f,0.f,0.f);
#pragma unroll
    for (int kp = 0; kp < KPP; kp++) {
        const int k  = pidx_s[p0 * KPP + kp];
        const float wa = w_s[k];
        const float wb = w_s[KK + k];
        const float4 ea = Ea[k * 64 + d4];
        const float4 eb = Eb[k * 64 + d4];
        aa.x = fmaf(wa, ea.x, aa.x); aa.y = fmaf(wa, ea.y, aa.y);
        aa.z = fmaf(wa, ea.z, aa.z); aa.w = fmaf(wa, ea.w, aa.w);
        ab.x = fmaf(wb, eb.x, ab.x); ab.y = fmaf(wb, eb.y, ab.y);
        ab.z = fmaf(wb, eb.z, ab.z); ab.w = fmaf(wb, eb.w, ab.w);
    }
    const float iva = winv_s[p0];
    const float ivb = winv_s[PP + p0];

    float* o = u_g + (size_t)row0 * 1024 + p0 * 256 + d4 * 4;
    *(float4*)o          = make_float4(aa.x*iva, aa.y*iva, aa.z*iva, aa.w*iva);
    *(float4*)(o + 1024) = make_float4(ab.x*ivb, ab.y*ivb, ab.z*ivb, ab.w*ivb);
}

// ===================== prep: gv = ln_g*v, constants =========================
__global__ void k_prep(const float* __restrict__ v, const float* __restrict__ c,
                       const float* __restrict__ ln_g, const float* __restrict__ ln_b)
{
    const int tid = threadIdx.x;             // 128
    const int p = tid >> 5, lane = tid & 31;
    float s4 = 0.f, s5 = 0.f;
#pragma unroll
    for (int i = 0; i < 8; i++) {
        const int col = p * 256 + lane + i * 32;
        const float vv = v[col];
        const float g  = ln_g[col] * vv;
        const float b  = ln_b[col] * vv;
        gv_g[col] = g;
        s4 += g; s5 += b;
    }
#pragma unroll
    for (int off = 16; off; off >>= 1) {
        s4 += __shfl_xor_sync(0xffffffffu, s4, off);
        s5 += __shfl_xor_sync(0xffffffffu, s5, off);
    }
    if (lane == 0) { cst_g[p] = s4; cst_g[4 + p] = s5 + c[p]; }
}

// ===================== GEMM (G1: mode 0, G2: mode 1) ========================
// CTA tile 128x128, K-chunk 32, 256 thr, thread tile 16 rows x 4 cols.
// As: [32 k][66 ULL] (64 rowpairs + pad), Bs: [32 k][132 f] (128 cols + pad).
#define ABUF (32 * 66)          // ULLs
#define BBUF (32 * 132)         // floats
#define GEMM_SMEM (2 * (ABUF * 8 + BBUF * 4))

__device__ __forceinline__ void g_stage(const float* aB, const float* bB,
                                        ULL* Adst, float* Bdst, int tid)
{
    // A: thread = rowpair (tid&63), k-group jg=tid>>6 (8 ks)
    const float4 x0 = *(const float4*)(aB);
    const float4 x1 = *(const float4*)(aB + 4);
    const float4 y0 = *(const float4*)(aB + 1024);
    const float4 y1 = *(const float4*)(aB + 1028);
    // B: thread = col (tid&127), k-half kh=tid>>7 (16 ks)
    float4 bq0 = *(const float4*)(bB);
    float4 bq1 = *(const float4*)(bB + 4);
    float4 bq2 = *(const float4*)(bB + 8);
    float4 bq3 = *(const float4*)(bB + 12);

    ULL* ad = Adst + ((tid >> 6) * 8) * 66 + (tid & 63);
    ad[0*66] = pack2(x0.x, y0.x);
    ad[1*66] = pack2(x0.y, y0.y);
    ad[2*66] = pack2(x0.z, y0.z);
    ad[3*66] = pack2(x0.w, y0.w);
    ad[4*66] = pack2(x1.x, y1.x);
    ad[5*66] = pack2(x1.y, y1.y);
    ad[6*66] = pack2(x1.z, y1.z);
    ad[7*66] = pack2(x1.w, y1.w);

    float* bd = Bdst + ((tid >> 7) * 16) * 132 + (tid & 127);
    bd[ 0*132] = bq0.x; bd[ 1*132] = bq0.y; bd[ 2*132] = bq0.z; bd[ 3*132] = bq0.w;
    bd[ 4*132] = bq1.x; bd[ 5*132] = bq1.y; bd[ 6*132] = bq1.z; bd[ 7*132] = bq1.w;
    bd[ 8*132] = bq2.x; bd[ 9*132] = bq2.y; bd[10*132] = bq2.z; bd[11*132] = bq2.w;
    bd[12*132] = bq3.x; bd[13*132] = bq3.y; bd[14*132] = bq3.z; bd[15*132] = bq3.w;
}

__device__ __forceinline__ void g_comp(ULL acc[8][4], const ULL* As_, const float* Bs_,
                                       int ty, int tx)
{
#pragma unroll 4
    for (int k = 0; k < 32; k++) {
        const ULL* ap = As_ + k * 66 + ty * 8;
        const ulonglong2 a0 = *(const ulonglong2*)(ap);
        const ulonglong2 a1 = *(const ulonglong2*)(ap + 2);
        const ulonglong2 a2 = *(const ulonglong2*)(ap + 4);
        const ulonglong2 a3 = *(const ulonglong2*)(ap + 6);
        const float4 bv = *(const float4*)(Bs_ + k * 132 + tx * 4);
        const ULL b0 = pack2(bv.x, bv.x);
        const ULL b1 = pack2(bv.y, bv.y);
        const ULL b2 = pack2(bv.z, bv.z);
        const ULL b3 = pack2(bv.w, bv.w);
        ULL ar[8] = { a0.x, a0.y, a1.x, a1.y, a2.x, a2.y, a3.x, a3.y };
#pragma unroll
        for (int rp = 0; rp < 8; rp++) {
            fma2(acc[rp][0], ar[rp], b0);
            fma2(acc[rp][1], ar[rp], b1);
            fma2(acc[rp][2], ar[rp], b2);
            fma2(acc[rp][3], ar[rp], b3);
        }
    }
}

__global__ __launch_bounds__(256, 2)
void k_gemm(const float* __restrict__ pW, const float* __restrict__ qW,
            const float* __restrict__ pb, int mode)
{
    extern __shared__ char sm[];
    ULL*   As0 = (ULL*)sm;
    float* Bs0 = (float*)(sm + ABUF * 8);
    ULL*   As1 = (ULL*)(sm + ABUF * 8 + BBUF * 4);
    float* Bs1 = (float*)(sm + 2 * (ABUF * 8) + BBUF * 4);
    ULL*   Asb[2] = { As0, As1 };
    float* Bsb[2] = { Bs0, Bs1 };

    const int tid = threadIdx.x;
    const int tx = tid & 31, ty = tid >> 5;
    const int m0 = blockIdx.x * 128;
    const int by = blockIdx.y;

    const float* Asrc; const float* Bp; const float* bias;
    float* outp; int bstride, ostride, kb;
    if (mode == 0) {
        const int p = by >> 1;
        Asrc = u_g; kb = p * 256;
        Bp = pW + (size_t)p * 65536 + (size_t)(by & 1) * 128 * 256;
        bstride = 256;
        bias = pb + p * 256 + (by & 1) * 128;
        outp = h_g + by * 128; ostride = 1024;
    } else {
        const int ks = blockIdx.z;
        Asrc = h_g; kb = ks * 256;
        Bp = qW + (size_t)by * 128 * 1024 + ks * 256;
        bstride = 1024;
        bias = nullptr;
        outp = s4_g + (size_t)ks * BT * 256 + by * 128; ostride = 256;
    }

    const float* aB0 = Asrc + (size_t)(m0 + 2 * (tid & 63)) * 1024 + kb + (tid >> 6) * 8;
    const float* bB0 = Bp + (size_t)(tid & 127) * bstride + (tid >> 7) * 16;

    ULL acc[8][4];
#pragma unroll
    for (int rp = 0; rp < 8; rp++)
#pragma unroll
        for (int cc = 0; cc < 4; cc++) acc[rp][cc] = 0ull;

    g_stage(aB0, bB0, Asb[0], Bsb[0], tid);
    __syncthreads();

#pragma unroll 1
    for (int t = 0; t < 8; t++) {
        if (t + 1 < 8)
            g_stage(aB0 + (t + 1) * 32, bB0 + (t + 1) * 32,
                    Asb[(t + 1) & 1], Bsb[(t + 1) & 1], tid);
        g_comp(acc, Asb[t & 1], Bsb[t & 1], ty, tx);
        __syncthreads();
    }

    if (bias) {
#pragma unroll
        for (int cc = 0; cc < 4; cc++) {
            const float b = bias[tx * 4 + cc];
            const ULL bp2 = pack2(b, b);
#pragma unroll
            for (int rp = 0; rp < 8; rp++) acc[rp][cc] = add2(acc[rp][cc], bp2);
        }
    }

#pragma unroll
    for (int rp = 0; rp < 8; rp++) {
        float lo0, hi0, lo1, hi1, lo2, hi2, lo3, hi3;
        unpack2(acc[rp][0], lo0, hi0);
        unpack2(acc[rp][1], lo1, hi1);
        unpack2(acc[rp][2], lo2, hi2);
        unpack2(acc[rp][3], lo3, hi3);
        const int row = m0 + ty * 16 + rp * 2;
        *(float4*)(outp + (size_t)row * ostride + tx * 4) =
            make_float4(lo0, lo1, lo2, lo3);
        *(float4*)(outp + (size_t)(row + 1) * ostride + tx * 4) =
            make_float4(hi0, hi1, hi2, hi3);
    }
}

// ===================== gate: LN-stats + sigmoid + scale (in place) ==========
__global__ __launch_bounds__(256)
void k_gate()
{
    const int tid = threadIdx.x;
    const int w = tid >> 5, lane = tid & 31;
    const int row = blockIdx.x * 2 + (w >> 2);
    const int p = w & 3;

    float xv[8], gv[8];
    const size_t base = (size_t)row * 1024 + p * 256;
#pragma unroll
    for (int i = 0; i < 8; i++) {
        const int col = lane + i * 32;
        xv[i] = h_g[base + col];
        gv[i] = gv_g[p * 256 + col];
    }
    float s1 = 0.f, s2 = 0.f, s3 = 0.f;
#pragma unroll
    for (int i = 0; i < 8; i++) {
        s1 += xv[i]; s2 += xv[i] * xv[i]; s3 += xv[i] * gv[i];
    }
#pragma unroll
    for (int off = 16; off; off >>= 1) {
        s1 += __shfl_xor_sync(0xffffffffu, s1, off);
        s2 += __shfl_xor_sync(0xffffffffu, s2, off);
        s3 += __shfl_xor_sync(0xffffffffu, s3, off);
    }
    const float m   = s1 * (1.0f / DD);
    const float var = s2 * (1.0f / DD) - m * m;
    const float rs  = rsqrtf(var + 1e-5f);
    const float dot = rs * (s3 - m * cst_g[p]) + cst_g[4 + p];
    const float alpha = 1.0f / (1.0f + __expf(-dot));
#pragma unroll
    for (int i = 0; i < 8; i++) h_g[base + lane + i * 32] = xv[i] * alpha;
}

// ===================== combine K-split partials + final LN ==================
__global__ __launch_bounds__(256)
void k_comb(const float* __restrict__ pjb, const float* __restrict__ og_,
            const float* __restrict__ ob_, float* __restrict__ out)
{
    __shared__ float redf[16 * 8 * 2];
    const int tid = threadIdx.x;
    const int w = tid >> 5, lane = tid & 31;
    const int bt0 = blockIdx.x * 16;

    const float b = pjb[tid];
    float x[16];
#pragma unroll
    for (int r = 0; r < 16; r++) {
        const size_t off = (size_t)(bt0 + r) * 256 + tid;
        x[r] = s4_g[off] + s4_g[off + (size_t)BT * 256]
             + s4_g[off + (size_t)2 * BT * 256] + s4_g[off + (size_t)3 * BT * 256] + b;
    }
#pragma unroll
    for (int r = 0; r < 16; r++) {
        float s1 = x[r], s2 = x[r] * x[r];
#pragma unroll
        for (int off = 16; off; off >>= 1) {
            s1 += __shfl_xor_sync(0xffffffffu, s1, off);
            s2 += __shfl_xor_sync(0xffffffffu, s2, off);
        }
        if (lane == 0) {
            redf[(r * 8 + w) * 2 + 0] = s1;
            redf[(r * 8 + w) * 2 + 1] = s2;
        }
    }
    __syncthreads();
    const float og = og_[tid], ob = ob_[tid];
#pragma unroll
    for (int r = 0; r < 16; r++) {
        float s1 = 0.f, s2 = 0.f;
#pragma unroll
        for (int ww = 0; ww < 8; ww++) {
            s1 += redf[(r * 8 + ww) * 2 + 0];
            s2 += redf[(r * 8 + ww) * 2 + 1];
        }
        const float m   = s1 * (1.0f / DD);
        const float var = s2 * (1.0f / DD) - m * m;
        const float rs  = rsqrtf(var + 1e-5f);
        out[(size_t)(bt0 + r) * 256 + tid] = (x[r] - m) * rs * og + ob;
    }
}

extern "C" void kernel_launch(void* const* d_in, const int* in_sizes, int n_in,
                              void* d_out, int out_size)
{
    (void)in_sizes; (void)n_in; (void)out_size;
    const float* E_S    = (const float*)d_in[0];
    const float* W      = (const float*)d_in[1];
    const int*   pidx   = (const int*)  d_in[2];
    const float* part_W = (const float*)d_in[3];
    const float* part_b = (const float*)d_in[4];
    const float* v      = (const float*)d_in[5];
    const float* c      = (const float*)d_in[6];
    const float* ln_g   = (const float*)d_in[7];
    const float* ln_b   = (const float*)d_in[8];
    const float* proj_W = (const float*)d_in[9];
    const float* proj_b = (const float*)d_in[10];
    const float* out_g  = (const float*)d_in[11];
    const float* out_b  = (const float*)d_in[12];
    float* out = (float*)d_out;

    cudaFuncSetAttribute(k_gemm, cudaFuncAttributeMaxDynamicSharedMemorySize, GEMM_SMEM);

    k_prep<<<1, 128>>>(v, c, ln_g, ln_b);
    k_seg<<<BT / 2, 256>>>(E_S, W, pidx);
    k_gemm<<<dim3(32, 8, 1), 256, GEMM_SMEM>>>(part_W, proj_W, part_b, 0);
    k_gate<<<BT / 2, 256>>>();
    k_gemm<<<dim3(32, 2, 4), 256, GEMM_SMEM>>>(part_W, proj_W, part_b, 1);
    k_comb<<<BT / 16, 256>>>(proj_b, out_g, out_b, out);
}

// round 10
// speedup vs baseline: 2.0860x; 1.6854x over previous
#include <cuda_runtime.h>
#include <cuda_bf16.h>
#include <math.h>
#include <stdint.h>

#define BT   4096
#define KK   64
#define DD   256
#define PP   4
#define KPP  16

// device scratch
__device__ __align__(16) __nv_bfloat16 u_hi[(size_t)BT * 1024];
__device__ __align__(16) __nv_bfloat16 u_lo[(size_t)BT * 1024];
__device__ __align__(16) float         h_g[(size_t)BT * 1024];   // u_hat fp32
__device__ __align__(16) __nv_bfloat16 z_hi[(size_t)BT * 1024];
__device__ __align__(16) __nv_bfloat16 z_lo[(size_t)BT * 1024];
__device__ __align__(16) float         s4_g[(size_t)4 * BT * 256];
__device__ __align__(16) __nv_bfloat16 pw_hi[4 * 256 * 256];
__device__ __align__(16) __nv_bfloat16 pw_lo[4 * 256 * 256];
__device__ __align__(16) __nv_bfloat16 qw_hi[256 * 1024];
__device__ __align__(16) __nv_bfloat16 qw_lo[256 * 1024];
__device__ __align__(16) float gv_g[1024];
__device__ float cst_g[8];

__device__ __forceinline__ uint32_t smem_u32(const void* p) {
    uint32_t a;
    asm("{ .reg .u64 t; cvta.to.shared.u64 t, %1; cvt.u32.u64 %0, t; }" : "=r"(a) : "l"(p));
    return a;
}
__device__ __forceinline__ void cp16(uint32_t dst, const void* src) {
    size_t g;
    asm("cvta.to.global.u64 %0, %1;" : "=l"(g) : "l"(src));
    asm volatile("cp.async.cg.shared.global [%0], [%1], 16;" :: "r"(dst), "l"(g) : "memory");
}
#define CP_COMMIT() asm volatile("cp.async.commit_group;" ::: "memory")
#define CP_WAIT1()  asm volatile("cp.async.wait_group 1;" ::: "memory")
#define CP_WAIT0()  asm volatile("cp.async.wait_group 0;" ::: "memory")

#define MMA_BF16(d, a, b0, b1) \
    asm volatile("mma.sync.aligned.m16n8k16.row.col.f32.bf16.bf16.f32 " \
        "{%0,%1,%2,%3}, {%4,%5,%6,%7}, {%8,%9}, {%0,%1,%2,%3};" \
        : "+f"((d)[0]), "+f"((d)[1]), "+f"((d)[2]), "+f"((d)[3]) \
        : "r"((a)[0]), "r"((a)[1]), "r"((a)[2]), "r"((a)[3]), "r"(b0), "r"(b1))

__device__ __forceinline__ void bsplit(float x, __nv_bfloat16& h, __nv_bfloat16& l) {
    h = __float2bfloat16(x);
    l = __float2bfloat16(x - __bfloat162float(h));
}

// ===================== K1: weighted segment-sum -> u hi/lo ==================
__global__ __launch_bounds__(256)
void k_seg(const float* __restrict__ E_S, const float* __restrict__ W,
           const int* __restrict__ part_idx)
{
    __shared__ float w_s[2 * KK];
    __shared__ float winv_s[2 * PP];
    __shared__ int   pidx_s[KK];

    const int tid = threadIdx.x;
    const int bx  = blockIdx.x;
    const int row0 = bx * 2;

    if (tid < KK)  pidx_s[tid] = part_idx[tid];
    if (tid < 2 * KK) w_s[tid] = W[(size_t)row0 * KK + tid];
    __syncthreads();
    if (tid < 2 * PP) {
        int r = tid >> 2, p = tid & 3;
        float s = 0.f;
#pragma unroll
        for (int kp = 0; kp < KPP; kp++) s += w_s[r * KK + pidx_s[p * KPP + kp]];
        winv_s[tid] = 1.0f / (s + 1e-6f);
    }
    __syncthreads();

    const int p0 = tid >> 6;
    const int d4 = tid & 63;
    const float4* Ea = (const float4*)(E_S + (size_t)row0 * KK * DD);
    const float4* Eb = Ea + (KK * DD / 4);

    float4 aa = make_float4(0.f,0.f,0.f,0.f);
    float4 ab = make_float4(0.f,0.f,0.f,0.f);
#pragma unroll
    for (int kp = 0; kp < KPP; kp++) {
        const int k  = pidx_s[p0 * KPP + kp];
        const float wa = w_s[k];
        const float wb = w_s[KK + k];
        const float4 ea = Ea[k * 64 + d4];
        const float4 eb = Eb[k * 64 + d4];
        aa.x = fmaf(wa, ea.x, aa.x); aa.y = fmaf(wa, ea.y, aa.y);
        aa.z = fmaf(wa, ea.z, aa.z); aa.w = fmaf(wa, ea.w, aa.w);
        ab.x = fmaf(wb, eb.x, ab.x); ab.y = fmaf(wb, eb.y, ab.y);
        ab.z = fmaf(wb, eb.z, ab.z); ab.w = fmaf(wb, eb.w, ab.w);
    }
    const float iva = winv_s[p0];
    const float ivb = winv_s[PP + p0];
    aa.x *= iva; aa.y *= iva; aa.z *= iva; aa.w *= iva;
    ab.x *= ivb; ab.y *= ivb; ab.z *= ivb; ab.w *= ivb;

    const size_t off0 = (size_t)row0 * 1024 + p0 * 256 + d4 * 4;
#pragma unroll
    for (int rr = 0; rr < 2; rr++) {
        const float4 s = rr ? ab : aa;
        const size_t off = off0 + (size_t)rr * 1024;
        __nv_bfloat16 h0,l0,h1,l1,h2,l2,h3,l3;
        bsplit(s.x,h0,l0); bsplit(s.y,h1,l1); bsplit(s.z,h2,l2); bsplit(s.w,h3,l3);
        __nv_bfloat162 hp0; hp0.x=h0; hp0.y=h1;
        __nv_bfloat162 hp1; hp1.x=h2; hp1.y=h3;
        __nv_bfloat162 lp0; lp0.x=l0; lp0.y=l1;
        __nv_bfloat162 lp1; lp1.x=l2; lp1.y=l3;
        *(__nv_bfloat162*)(u_hi + off)     = hp0;
        *(__nv_bfloat162*)(u_hi + off + 2) = hp1;
        *(__nv_bfloat162*)(u_lo + off)     = lp0;
        *(__nv_bfloat162*)(u_lo + off + 2) = lp1;
    }
}

// ===================== prep: gv/cst + weight bf16 split =====================
__global__ void k_prep(const float* __restrict__ v, const float* __restrict__ c,
                       const float* __restrict__ ln_g, const float* __restrict__ ln_b)
{
    const int tid = threadIdx.x;             // 128
    const int p = tid >> 5, lane = tid & 31;
    float s4 = 0.f, s5 = 0.f;
#pragma unroll
    for (int i = 0; i < 8; i++) {
        const int col = p * 256 + lane + i * 32;
        const float vv = v[col];
        const float g  = ln_g[col] * vv;
        const float b  = ln_b[col] * vv;
        gv_g[col] = g;
        s4 += g; s5 += b;
    }
#pragma unroll
    for (int off = 16; off; off >>= 1) {
        s4 += __shfl_xor_sync(0xffffffffu, s4, off);
        s5 += __shfl_xor_sync(0xffffffffu, s5, off);
    }
    if (lane == 0) { cst_g[p] = s4; cst_g[4 + p] = s5 + c[p]; }
}

__global__ __launch_bounds__(256)
void k_wconv(const float* __restrict__ part_W, const float* __restrict__ proj_W)
{
    const int i0 = blockIdx.x * 256 + threadIdx.x;
#pragma unroll
    for (int j = 0; j < 4; j++) {
        const int i = i0 + j * 131072;
        if (i < 262144) {
            __nv_bfloat16 h, l; bsplit(part_W[i], h, l);
            pw_hi[i] = h; pw_lo[i] = l;
        } else {
            const int q = i - 262144;
            __nv_bfloat16 h, l; bsplit(proj_W[q], h, l);
            qw_hi[q] = h; qw_lo[q] = l;
        }
    }
}

// ===================== bf16-split HMMA GEMM =================================
// smem: 2 stages x (Ahi 10240 | Alo 10240 | Bhi 10240 | Blo 10240) + bias 512
// tile layouts: 128 rows x 32 k bf16, row pitch 80 B
#define GEMM_SMEM (81920 + 512)

__global__ __launch_bounds__(256, 2)
void k_gemm(const float* __restrict__ part_b_, int mode)
{
    extern __shared__ char sm[];
    float* bias_s = (float*)(sm + 81920);

    const int tid = threadIdx.x;
    const int w = tid >> 5, lane = tid & 31;
    const int gid = lane >> 2, tig = lane & 3;
    const int m0 = blockIdx.x * 128;

    const __nv_bfloat16 *Ah, *Al, *Bh, *Bl;
    int akoff, bkoff, bstride;
    float* outp; int ostride;
    if (mode == 0) {
        const int p = blockIdx.y >> 1, nh = blockIdx.y & 1;
        Ah = u_hi; Al = u_lo;
        Bh = pw_hi + p * 65536 + nh * 128 * 256;
        Bl = pw_lo + p * 65536 + nh * 128 * 256;
        akoff = p * 256; bkoff = 0; bstride = 256;
        outp = h_g + p * 256 + nh * 128; ostride = 1024;
        if (tid < 128) bias_s[tid] = part_b_[p * 256 + nh * 128 + tid];
    } else {
        const int nb = blockIdx.y, ks = blockIdx.z;
        Ah = z_hi; Al = z_lo;
        Bh = qw_hi + (size_t)nb * 128 * 1024;
        Bl = qw_lo + (size_t)nb * 128 * 1024;
        akoff = ks * 256; bkoff = ks * 256; bstride = 1024;
        outp = s4_g + (size_t)ks * BT * 256 + nb * 128; ostride = 256;
    }

    // acc
    float acc[2][8][4];
#pragma unroll
    for (int mt = 0; mt < 2; mt++)
#pragma unroll
        for (int nt = 0; nt < 8; nt++)
#pragma unroll
            for (int q = 0; q < 4; q++) acc[mt][nt][q] = 0.f;

    // staging lambda
    auto issue = [&](int c) {
        const int kA = akoff + c * 32, kB = bkoff + c * 32;
        char* base = sm + (c & 1) * 40960;
#pragma unroll
        for (int j = 0; j < 2; j++) {
            const int idx = tid + j * 256;
            const int row = idx >> 2, q = idx & 3;
            const uint32_t d = smem_u32(base + row * 80 + q * 16);
            cp16(d,          Ah + (size_t)(m0 + row) * 1024 + kA + q * 8);
            cp16(d + 10240,  Al + (size_t)(m0 + row) * 1024 + kA + q * 8);
            cp16(d + 20480,  Bh + (size_t)row * bstride + kB + q * 8);
            cp16(d + 30720,  Bl + (size_t)row * bstride + kB + q * 8);
        }
        CP_COMMIT();
    };

    issue(0);
    issue(1);

    const int mrow = (w & 3) * 32;
    const int ncol = (w >> 2) * 64;

#pragma unroll 1
    for (int c = 0; c < 8; c++) {
        if (c == 7) { CP_WAIT0(); } else { CP_WAIT1(); }
        __syncthreads();

        const char* base = sm + (c & 1) * 40960;
#pragma unroll
        for (int st = 0; st < 2; st++) {
            uint32_t ahf[2][4], alf[2][4];
#pragma unroll
            for (int mt = 0; mt < 2; mt++) {
                const char* pa = base + (mrow + mt * 16 + gid) * 80 + st * 32 + tig * 4;
                ahf[mt][0] = *(const uint32_t*)(pa);
                ahf[mt][1] = *(const uint32_t*)(pa + 8 * 80);
                ahf[mt][2] = *(const uint32_t*)(pa + 16);
                ahf[mt][3] = *(const uint32_t*)(pa + 8 * 80 + 16);
                const char* pl = pa + 10240;
                alf[mt][0] = *(const uint32_t*)(pl);
                alf[mt][1] = *(const uint32_t*)(pl + 8 * 80);
                alf[mt][2] = *(const uint32_t*)(pl + 16);
                alf[mt][3] = *(const uint32_t*)(pl + 8 * 80 + 16);
            }
#pragma unroll
            for (int nt = 0; nt < 8; nt++) {
                const char* pb = base + 20480 + (ncol + nt * 8 + gid) * 80 + st * 32 + tig * 4;
                const uint32_t bh0 = *(const uint32_t*)(pb);
                const uint32_t bh1 = *(const uint32_t*)(pb + 16);
                const uint32_t bl0 = *(const uint32_t*)(pb + 10240);
                const uint32_t bl1 = *(const uint32_t*)(pb + 10240 + 16);
#pragma unroll
                for (int mt = 0; mt < 2; mt++) {
                    MMA_BF16(acc[mt][nt], ahf[mt], bh0, bh1);
                    MMA_BF16(acc[mt][nt], ahf[mt], bl0, bl1);
                    MMA_BF16(acc[mt][nt], alf[mt], bh0, bh1);
                }
            }
        }
        __syncthreads();
        if (c + 2 < 8) issue(c + 2);
    }

    // epilogue
#pragma unroll
    for (int mt = 0; mt < 2; mt++) {
        const int r0 = m0 + mrow + mt * 16 + gid;
#pragma unroll
        for (int nt = 0; nt < 8; nt++) {
            const int c0 = ncol + nt * 8 + tig * 2;
            float d0 = acc[mt][nt][0], d1 = acc[mt][nt][1];
            float d2 = acc[mt][nt][2], d3 = acc[mt][nt][3];
            if (mode == 0) {
                const float b0 = bias_s[c0], b1 = bias_s[c0 + 1];
                d0 += b0; d1 += b1; d2 += b0; d3 += b1;
            }
            *(float2*)(outp + (size_t)r0 * ostride + c0)       = make_float2(d0, d1);
            *(float2*)(outp + (size_t)(r0 + 8) * ostride + c0) = make_float2(d2, d3);
        }
    }
}

// ===================== gate: LN stats + sigmoid; write Z hi/lo ==============
__global__ __launch_bounds__(256)
void k_gate()
{
    const int tid = threadIdx.x;
    const int w = tid >> 5, lane = tid & 31;
    const int row = blockIdx.x * 2 + (w >> 2);
    const int p = w & 3;

    float xv[8], gv[8];
    const size_t base = (size_t)row * 1024 + p * 256;
#pragma unroll
    for (int i = 0; i < 8; i++) {
        const int col = lane + i * 32;
        xv[i] = h_g[base + col];
        gv[i] = gv_g[p * 256 + col];
    }
    float s1 = 0.f, s2 = 0.f, s3 = 0.f;
#pragma unroll
    for (int i = 0; i < 8; i++) {
        s1 += xv[i]; s2 += xv[i] * xv[i]; s3 += xv[i] * gv[i];
    }
#pragma unroll
    for (int off = 16; off; off >>= 1) {
        s1 += __shfl_xor_sync(0xffffffffu, s1, off);
        s2 += __shfl_xor_sync(0xffffffffu, s2, off);
        s3 += __shfl_xor_sync(0xffffffffu, s3, off);
    }
    const float m   = s1 * (1.0f / DD);
    const float var = s2 * (1.0f / DD) - m * m;
    const float rs  = rsqrtf(var + 1e-5f);
    const float dot = rs * (s3 - m * cst_g[p]) + cst_g[4 + p];
    const float alpha = 1.0f / (1.0f + __expf(-dot));
#pragma unroll
    for (int i = 0; i < 8; i++) {
        const float z = xv[i] * alpha;
        __nv_bfloat16 h, l; bsplit(z, h, l);
        z_hi[base + lane + i * 32] = h;
        z_lo[base + lane + i * 32] = l;
    }
}

// ===================== combine K-split partials + final LN ==================
__global__ __launch_bounds__(256)
void k_comb(const float* __restrict__ pjb, const float* __restrict__ og_,
            const float* __restrict__ ob_, float* __restrict__ out)
{
    __shared__ float redf[16 * 8 * 2];
    const int tid = threadIdx.x;
    const int w = tid >> 5, lane = tid & 31;
    const int bt0 = blockIdx.x * 16;

    const float b = pjb[tid];
    float x[16];
#pragma unroll
    for (int r = 0; r < 16; r++) {
        const size_t off = (size_t)(bt0 + r) * 256 + tid;
        x[r] = s4_g[off] + s4_g[off + (size_t)BT * 256]
             + s4_g[off + (size_t)2 * BT * 256] + s4_g[off + (size_t)3 * BT * 256] + b;
    }
#pragma unroll
    for (int r = 0; r < 16; r++) {
        float s1 = x[r], s2 = x[r] * x[r];
#pragma unroll
        for (int off = 16; off; off >>= 1) {
            s1 += __shfl_xor_sync(0xffffffffu, s1, off);
            s2 += __shfl_xor_sync(0xffffffffu, s2, off);
        }
        if (lane == 0) {
            redf[(r * 8 + w) * 2 + 0] = s1;
            redf[(r * 8 + w) * 2 + 1] = s2;
        }
    }
    __syncthreads();
    const float og = og_[tid], ob = ob_[tid];
#pragma unroll
    for (int r = 0; r < 16; r++) {
        float s1 = 0.f, s2 = 0.f;
#pragma unroll
        for (int ww = 0; ww < 8; ww++) {
            s1 += redf[(r * 8 + ww) * 2 + 0];
            s2 += redf[(r * 8 + ww) * 2 + 1];
        }
        const float m   = s1 * (1.0f / DD);
        const float var = s2 * (1.0f / DD) - m * m;
        const float rs  = rsqrtf(var + 1e-5f);
        out[(size_t)(bt0 + r) * 256 + tid] = (x[r] - m) * rs * og + ob;
    }
}

extern "C" void kernel_launch(void* const* d_in, const int* in_sizes, int n_in,
                              void* d_out, int out_size)
{
    (void)in_sizes; (void)n_in; (void)out_size;
    const float* E_S    = (const float*)d_in[0];
    const float* W      = (const float*)d_in[1];
    const int*   pidx   = (const int*)  d_in[2];
    const float* part_W = (const float*)d_in[3];
    const float* part_b = (const float*)d_in[4];
    const float* v      = (const float*)d_in[5];
    const float* c      = (const float*)d_in[6];
    const float* ln_g   = (const float*)d_in[7];
    const float* ln_b   = (const float*)d_in[8];
    const float* proj_W = (const float*)d_in[9];
    const float* proj_b = (const float*)d_in[10];
    const float* out_g  = (const float*)d_in[11];
    const float* out_b  = (const float*)d_in[12];
    float* out = (float*)d_out;

    cudaFuncSetAttribute(k_gemm, cudaFuncAttributeMaxDynamicSharedMemorySize, GEMM_SMEM);

    k_prep<<<1, 128>>>(v, c, ln_g, ln_b);
    k_wconv<<<512, 256>>>(part_W, proj_W);
    k_seg<<<BT / 2, 256>>>(E_S, W, pidx);
    k_gemm<<<dim3(32, 8, 1), 256, GEMM_SMEM>>>(part_b, 0);
    k_gate<<<BT / 2, 256>>>();
    k_gemm<<<dim3(32, 2, 4), 256, GEMM_SMEM>>>(part_b, 1);
    k_comb<<<BT / 16, 256>>>(proj_b, out_g, out_b, out);
}

// round 11
// speedup vs baseline: 2.1778x; 1.0440x over previous
#include <cuda_runtime.h>
#include <cuda_bf16.h>
#include <math.h>
#include <stdint.h>

#define BT   4096
#define KK   64
#define DD   256
#define PP   4
#define KPP  16

// device scratch
__device__ __align__(16) __nv_bfloat16 u_hi[(size_t)BT * 1024];
__device__ __align__(16) __nv_bfloat16 u_lo[(size_t)BT * 1024];
__device__ __align__(16) __nv_bfloat16 z_hi[(size_t)BT * 1024];
__device__ __align__(16) __nv_bfloat16 z_lo[(size_t)BT * 1024];
__device__ __align__(16) float         s4_g[(size_t)4 * BT * 256];
__device__ __align__(16) __nv_bfloat16 pw_hi[4 * 256 * 256];
__device__ __align__(16) __nv_bfloat16 pw_lo[4 * 256 * 256];
__device__ __align__(16) __nv_bfloat16 qw_hi[256 * 1024];
__device__ __align__(16) __nv_bfloat16 qw_lo[256 * 1024];
__device__ __align__(16) float gv_g[1024];
__device__ float cst_g[8];

__device__ __forceinline__ uint32_t smem_u32(const void* p) {
    uint32_t a;
    asm("{ .reg .u64 t; cvta.to.shared.u64 t, %1; cvt.u32.u64 %0, t; }" : "=r"(a) : "l"(p));
    return a;
}
__device__ __forceinline__ void cp16(uint32_t dst, const void* src) {
    size_t g;
    asm("cvta.to.global.u64 %0, %1;" : "=l"(g) : "l"(src));
    asm volatile("cp.async.cg.shared.global [%0], [%1], 16;" :: "r"(dst), "l"(g) : "memory");
}
#define CP_COMMIT() asm volatile("cp.async.commit_group;" ::: "memory")
#define CP_WAIT1()  asm volatile("cp.async.wait_group 1;" ::: "memory")
#define CP_WAIT0()  asm volatile("cp.async.wait_group 0;" ::: "memory")

#define MMA_BF16(d, a, b0, b1) \
    asm volatile("mma.sync.aligned.m16n8k16.row.col.f32.bf16.bf16.f32 " \
        "{%0,%1,%2,%3}, {%4,%5,%6,%7}, {%8,%9}, {%0,%1,%2,%3};" \
        : "+f"((d)[0]), "+f"((d)[1]), "+f"((d)[2]), "+f"((d)[3]) \
        : "r"((a)[0]), "r"((a)[1]), "r"((a)[2]), "r"((a)[3]), "r"(b0), "r"(b1))

__device__ __forceinline__ void ldm_x4(uint32_t& r0, uint32_t& r1, uint32_t& r2, uint32_t& r3,
                                       uint32_t a) {
    asm volatile("ldmatrix.sync.aligned.m8n8.x4.shared.b16 {%0,%1,%2,%3}, [%4];"
                 : "=r"(r0), "=r"(r1), "=r"(r2), "=r"(r3) : "r"(a));
}

__device__ __forceinline__ void bsplit(float x, __nv_bfloat16& h, __nv_bfloat16& l) {
    h = __float2bfloat16(x);
    l = __float2bfloat16(x - __bfloat162float(h));
}

// ===================== K1: weighted segment-sum -> u hi/lo ==================
__global__ __launch_bounds__(256)
void k_seg(const float* __restrict__ E_S, const float* __restrict__ W,
           const int* __restrict__ part_idx)
{
    __shared__ float w_s[2 * KK];
    __shared__ float winv_s[2 * PP];
    __shared__ int   pidx_s[KK];

    const int tid = threadIdx.x;
    const int bx  = blockIdx.x;
    const int row0 = bx * 2;

    if (tid < KK)  pidx_s[tid] = part_idx[tid];
    if (tid < 2 * KK) w_s[tid] = W[(size_t)row0 * KK + tid];
    __syncthreads();
    if (tid < 2 * PP) {
        int r = tid >> 2, p = tid & 3;
        float s = 0.f;
#pragma unroll
        for (int kp = 0; kp < KPP; kp++) s += w_s[r * KK + pidx_s[p * KPP + kp]];
        winv_s[tid] = 1.0f / (s + 1e-6f);
    }
    __syncthreads();

    const int p0 = tid >> 6;
    const int d4 = tid & 63;
    const float4* Ea = (const float4*)(E_S + (size_t)row0 * KK * DD);
    const float4* Eb = Ea + (KK * DD / 4);

    float4 aa = make_float4(0.f,0.f,0.f,0.f);
    float4 ab = make_float4(0.f,0.f,0.f,0.f);
#pragma unroll
    for (int kp = 0; kp < KPP; kp++) {
        const int k  = pidx_s[p0 * KPP + kp];
        const float wa = w_s[k];
        const float wb = w_s[KK + k];
        const float4 ea = Ea[k * 64 + d4];
        const float4 eb = Eb[k * 64 + d4];
        aa.x = fmaf(wa, ea.x, aa.x); aa.y = fmaf(wa, ea.y, aa.y);
        aa.z = fmaf(wa, ea.z, aa.z); aa.w = fmaf(wa, ea.w, aa.w);
        ab.x = fmaf(wb, eb.x, ab.x); ab.y = fmaf(wb, eb.y, ab.y);
        ab.z = fmaf(wb, eb.z, ab.z); ab.w = fmaf(wb, eb.w, ab.w);
    }
    const float iva = winv_s[p0];
    const float ivb = winv_s[PP + p0];
    aa.x *= iva; aa.y *= iva; aa.z *= iva; aa.w *= iva;
    ab.x *= ivb; ab.y *= ivb; ab.z *= ivb; ab.w *= ivb;

    const size_t off0 = (size_t)row0 * 1024 + p0 * 256 + d4 * 4;
#pragma unroll
    for (int rr = 0; rr < 2; rr++) {
        const float4 s = rr ? ab : aa;
        const size_t off = off0 + (size_t)rr * 1024;
        __nv_bfloat16 h0,l0,h1,l1,h2,l2,h3,l3;
        bsplit(s.x,h0,l0); bsplit(s.y,h1,l1); bsplit(s.z,h2,l2); bsplit(s.w,h3,l3);
        __nv_bfloat162 hp0; hp0.x=h0; hp0.y=h1;
        __nv_bfloat162 hp1; hp1.x=h2; hp1.y=h3;
        __nv_bfloat162 lp0; lp0.x=l0; lp0.y=l1;
        __nv_bfloat162 lp1; lp1.x=l2; lp1.y=l3;
        *(__nv_bfloat162*)(u_hi + off)     = hp0;
        *(__nv_bfloat162*)(u_hi + off + 2) = hp1;
        *(__nv_bfloat162*)(u_lo + off)     = lp0;
        *(__nv_bfloat162*)(u_lo + off + 2) = lp1;
    }
}

// ===================== prep: gv/cst + weight bf16 split =====================
__global__ void k_prep(const float* __restrict__ v, const float* __restrict__ c,
                       const float* __restrict__ ln_g, const float* __restrict__ ln_b)
{
    const int tid = threadIdx.x;             // 128
    const int p = tid >> 5, lane = tid & 31;
    float s4 = 0.f, s5 = 0.f;
#pragma unroll
    for (int i = 0; i < 8; i++) {
        const int col = p * 256 + lane + i * 32;
        const float vv = v[col];
        const float g  = ln_g[col] * vv;
        const float b  = ln_b[col] * vv;
        gv_g[col] = g;
        s4 += g; s5 += b;
    }
#pragma unroll
    for (int off = 16; off; off >>= 1) {
        s4 += __shfl_xor_sync(0xffffffffu, s4, off);
        s5 += __shfl_xor_sync(0xffffffffu, s5, off);
    }
    if (lane == 0) { cst_g[p] = s4; cst_g[4 + p] = s5 + c[p]; }
}

__global__ __launch_bounds__(256)
void k_wconv(const float* __restrict__ part_W, const float* __restrict__ proj_W)
{
    const int i0 = blockIdx.x * 256 + threadIdx.x;
#pragma unroll
    for (int j = 0; j < 4; j++) {
        const int i = i0 + j * 131072;
        if (i < 262144) {
            __nv_bfloat16 h, l; bsplit(part_W[i], h, l);
            pw_hi[i] = h; pw_lo[i] = l;
        } else {
            const int q = i - 262144;
            __nv_bfloat16 h, l; bsplit(proj_W[q], h, l);
            qw_hi[q] = h; qw_lo[q] = l;
        }
    }
}

// ===================== unified 128x256 HMMA GEMM =============================
// smem per stage (pitch 80B): Ahi 10240 | Alo 10240 | Bhi 20480 | Blo 20480 = 61440
// x2 stages = 122880; then bias[256]f, gvs[256]f, stats[128][12]f, alpha[128]f
#define STG      61440
#define SM_BIAS  122880
#define SM_GVS   (SM_BIAS + 1024)
#define SM_STATS (SM_GVS + 1024)
#define SM_ALPH  (SM_STATS + 6144)
#define GEMM_SMEM (SM_ALPH + 512)

__global__ __launch_bounds__(512, 1)
void k_gemm(const float* __restrict__ part_b_, int mode)
{
    extern __shared__ char sm[];
    float* bias_s  = (float*)(sm + SM_BIAS);
    float* gvs_s   = (float*)(sm + SM_GVS);
    float* stats_s = (float*)(sm + SM_STATS);   // [128][12]
    float* alpha_s = (float*)(sm + SM_ALPH);    // [128]

    const int tid = threadIdx.x;
    const int w = tid >> 5, lane = tid & 31;
    const int gid = lane >> 2, tig = lane & 3;
    const int m0 = blockIdx.x * 128;
    const int by = blockIdx.y;     // mode0: part; mode1: K-split

    const __nv_bfloat16 *Ah, *Al, *Bh, *Bl;
    int akoff, bkoff, bstride;
    if (mode == 0) {
        Ah = u_hi; Al = u_lo;
        Bh = pw_hi + by * 65536; Bl = pw_lo + by * 65536;
        akoff = by * 256; bkoff = 0; bstride = 256;
        if (tid < 256) {
            bias_s[tid] = part_b_[by * 256 + tid];
            gvs_s[tid]  = gv_g[by * 256 + tid];
        }
    } else {
        Ah = z_hi; Al = z_lo;
        Bh = qw_hi; Bl = qw_lo;
        akoff = by * 256; bkoff = by * 256; bstride = 1024;
    }

    float acc[2][8][4];
#pragma unroll
    for (int mt = 0; mt < 2; mt++)
#pragma unroll
        for (int nt = 0; nt < 8; nt++)
#pragma unroll
            for (int q = 0; q < 4; q++) acc[mt][nt][q] = 0.f;

    auto issue = [&](int c) {
        const int kA = akoff + c * 32, kB = bkoff + c * 32;
        char* base = sm + (c & 1) * STG;
        {   // A: 128 rows x 4 chunks = 512 ops, 1 per thread (hi+lo)
            const int row = tid >> 2, q = tid & 3;
            const uint32_t d = smem_u32(base + row * 80 + q * 16);
            cp16(d,         Ah + (size_t)(m0 + row) * 1024 + kA + q * 8);
            cp16(d + 10240, Al + (size_t)(m0 + row) * 1024 + kA + q * 8);
        }
#pragma unroll
        for (int j = 0; j < 2; j++) {  // B: 256 rows x 4 = 1024 ops
            const int idx = tid + j * 512;
            const int row = idx >> 2, q = idx & 3;
            const uint32_t d = smem_u32(base + 20480 + row * 80 + q * 16);
            cp16(d,         Bh + (size_t)row * bstride + kB + q * 8);
            cp16(d + 20480, Bl + (size_t)row * bstride + kB + q * 8);
        }
        CP_COMMIT();
    };

    issue(0);
    issue(1);

    const int mrow = (w & 3) * 32;
    const int ncol = (w >> 2) * 64;
    const int lr = lane & 7, lq = lane >> 3;   // ldmatrix row / quadrant

#pragma unroll 1
    for (int c = 0; c < 8; c++) {
        if (c == 7) { CP_WAIT0(); } else { CP_WAIT1(); }
        __syncthreads();

        char* base = sm + (c & 1) * STG;
#pragma unroll
        for (int st = 0; st < 2; st++) {
            uint32_t ah[2][4], al[2][4];
#pragma unroll
            for (int mt = 0; mt < 2; mt++) {
                // quadrants: q0 rows m..7/k0, q1 rows m+8../k0, q2 rows m../k8, q3 rows m+8../k8
                const uint32_t a = smem_u32(base + (mrow + mt * 16 + (lq & 1) * 8 + lr) * 80
                                            + st * 32 + (lq >> 1) * 16);
                ldm_x4(ah[mt][0], ah[mt][1], ah[mt][2], ah[mt][3], a);
                ldm_x4(al[mt][0], al[mt][1], al[mt][2], al[mt][3], a + 10240);
            }
#pragma unroll
            for (int nt2 = 0; nt2 < 4; nt2++) {
                // quadrants: q0 (n0..7,k0), q1 (n0..7,k8), q2 (n8..15,k0), q3 (n8..15,k8)
                const uint32_t bAddr = smem_u32(base + 20480
                                      + (ncol + nt2 * 16 + (lq >> 1) * 8 + lr) * 80
                                      + st * 32 + (lq & 1) * 16);
                uint32_t bh0, bh1, bh2, bh3, bl0, bl1, bl2, bl3;
                ldm_x4(bh0, bh1, bh2, bh3, bAddr);
                ldm_x4(bl0, bl1, bl2, bl3, bAddr + 20480);
#pragma unroll
                for (int mt = 0; mt < 2; mt++) {
                    MMA_BF16(acc[mt][2 * nt2],     ah[mt], bh0, bh1);
                    MMA_BF16(acc[mt][2 * nt2],     ah[mt], bl0, bl1);
                    MMA_BF16(acc[mt][2 * nt2],     al[mt], bh0, bh1);
                    MMA_BF16(acc[mt][2 * nt2 + 1], ah[mt], bh2, bh3);
                    MMA_BF16(acc[mt][2 * nt2 + 1], ah[mt], bl2, bl3);
                    MMA_BF16(acc[mt][2 * nt2 + 1], al[mt], bh2, bh3);
                }
            }
        }
        __syncthreads();
        if (c + 2 < 8) issue(c + 2);
    }

    if (mode == 0) {
        // ---- fused gate epilogue ----
        // x = acc + bias; per-thread 4 rows: mt*16 + gid (+8)
        float s1[4], s2[4], s3[4];
#pragma unroll
        for (int i = 0; i < 4; i++) { s1[i] = 0.f; s2[i] = 0.f; s3[i] = 0.f; }
#pragma unroll
        for (int mt = 0; mt < 2; mt++)
#pragma unroll
            for (int nt = 0; nt < 8; nt++) {
                const int c0 = ncol + nt * 8 + tig * 2;
                const float b0 = bias_s[c0], b1 = bias_s[c0 + 1];
                const float g0 = gvs_s[c0],  g1 = gvs_s[c0 + 1];
                const float x0 = acc[mt][nt][0] + b0, x1 = acc[mt][nt][1] + b1;
                const float x2 = acc[mt][nt][2] + b0, x3 = acc[mt][nt][3] + b1;
                acc[mt][nt][0] = x0; acc[mt][nt][1] = x1;
                acc[mt][nt][2] = x2; acc[mt][nt][3] = x3;
                const int i0 = mt * 2, i1 = mt * 2 + 1;
                s1[i0] += x0 + x1; s2[i0] += x0*x0 + x1*x1; s3[i0] += x0*g0 + x1*g1;
                s1[i1] += x2 + x3; s2[i1] += x2*x2 + x3*x3; s3[i1] += x2*g0 + x3*g1;
            }
        // quad reduce (lanes with same gid, tig 0..3)
#pragma unroll
        for (int i = 0; i < 4; i++) {
#pragma unroll
            for (int off = 1; off < 4; off <<= 1) {
                s1[i] += __shfl_xor_sync(0xffffffffu, s1[i], off);
                s2[i] += __shfl_xor_sync(0xffffffffu, s2[i], off);
                s3[i] += __shfl_xor_sync(0xffffffffu, s3[i], off);
            }
        }
        const int cg = w >> 2;
        if (tig == 0) {
#pragma unroll
            for (int i = 0; i < 4; i++) {
                const int row = mrow + (i >> 1) * 16 + (i & 1) * 8 + gid;
                stats_s[row * 12 + cg * 3 + 0] = s1[i];
                stats_s[row * 12 + cg * 3 + 1] = s2[i];
                stats_s[row * 12 + cg * 3 + 2] = s3[i];
            }
        }
        __syncthreads();
        if (tid < 128) {
            float S1 = 0.f, S2 = 0.f, S3 = 0.f;
#pragma unroll
            for (int g = 0; g < 4; g++) {
                S1 += stats_s[tid * 12 + g * 3 + 0];
                S2 += stats_s[tid * 12 + g * 3 + 1];
                S3 += stats_s[tid * 12 + g * 3 + 2];
            }
            const float m   = S1 * (1.0f / DD);
            const float var = S2 * (1.0f / DD) - m * m;
            const float rs  = rsqrtf(var + 1e-5f);
            const float dot = rs * (S3 - m * cst_g[by]) + cst_g[4 + by];
            alpha_s[tid] = 1.0f / (1.0f + __expf(-dot));
        }
        __syncthreads();
        // scale + bf16-split store Z
#pragma unroll
        for (int mt = 0; mt < 2; mt++) {
            const int rA = mrow + mt * 16 + gid;
            const float alA = alpha_s[rA], alB = alpha_s[rA + 8];
#pragma unroll
            for (int nt = 0; nt < 8; nt++) {
                const int c0 = ncol + nt * 8 + tig * 2;
                const size_t gA = (size_t)(m0 + rA) * 1024 + by * 256 + c0;
                const size_t gB = gA + (size_t)8 * 1024;
                __nv_bfloat16 h0,l0,h1,l1;
                bsplit(acc[mt][nt][0] * alA, h0, l0);
                bsplit(acc[mt][nt][1] * alA, h1, l1);
                __nv_bfloat162 hp; hp.x=h0; hp.y=h1;
                __nv_bfloat162 lp; lp.x=l0; lp.y=l1;
                *(__nv_bfloat162*)(z_hi + gA) = hp;
                *(__nv_bfloat162*)(z_lo + gA) = lp;
                bsplit(acc[mt][nt][2] * alB, h0, l0);
                bsplit(acc[mt][nt][3] * alB, h1, l1);
                hp.x=h0; hp.y=h1; lp.x=l0; lp.y=l1;
                *(__nv_bfloat162*)(z_hi + gB) = hp;
                *(__nv_bfloat162*)(z_lo + gB) = lp;
            }
        }
    } else {
        float* outp = s4_g + (size_t)by * BT * 256;
#pragma unroll
        for (int mt = 0; mt < 2; mt++) {
            const int r0 = m0 + mrow + mt * 16 + gid;
#pragma unroll
            for (int nt = 0; nt < 8; nt++) {
                const int c0 = ncol + nt * 8 + tig * 2;
                *(float2*)(outp + (size_t)r0 * 256 + c0) =
                    make_float2(acc[mt][nt][0], acc[mt][nt][1]);
                *(float2*)(outp + (size_t)(r0 + 8) * 256 + c0) =
                    make_float2(acc[mt][nt][2], acc[mt][nt][3]);
            }
        }
    }
}

// ===================== combine K-split partials + final LN ==================
__global__ __launch_bounds__(256)
void k_comb(const float* __restrict__ pjb, const float* __restrict__ og_,
            const float* __restrict__ ob_, float* __restrict__ out)
{
    __shared__ float redf[16 * 8 * 2];
    const int tid = threadIdx.x;
    const int w = tid >> 5, lane = tid & 31;
    const int bt0 = blockIdx.x * 16;

    const float b = pjb[tid];
    float x[16];
#pragma unroll
    for (int r = 0; r < 16; r++) {
        const size_t off = (size_t)(bt0 + r) * 256 + tid;
        x[r] = s4_g[off] + s4_g[off + (size_t)BT * 256]
             + s4_g[off + (size_t)2 * BT * 256] + s4_g[off + (size_t)3 * BT * 256] + b;
    }
#pragma unroll
    for (int r = 0; r < 16; r++) {
        float s1 = x[r], s2 = x[r] * x[r];
#pragma unroll
        for (int off = 16; off; off >>= 1) {
            s1 += __shfl_xor_sync(0xffffffffu, s1, off);
            s2 += __shfl_xor_sync(0xffffffffu, s2, off);
        }
        if (lane == 0) {
            redf[(r * 8 + w) * 2 + 0] = s1;
            redf[(r * 8 + w) * 2 + 1] = s2;
        }
    }
    __syncthreads();
    const float og = og_[tid], ob = ob_[tid];
#pragma unroll
    for (int r = 0; r < 16; r++) {
        float s1 = 0.f, s2 = 0.f;
#pragma unroll
        for (int ww = 0; ww < 8; ww++) {
            s1 += redf[(r * 8 + ww) * 2 + 0];
            s2 += redf[(r * 8 + ww) * 2 + 1];
        }
        const float m   = s1 * (1.0f / DD);
        const float var = s2 * (1.0f / DD) - m * m;
        const float rs  = rsqrtf(var + 1e-5f);
        out[(size_t)(bt0 + r) * 256 + tid] = (x[r] - m) * rs * og + ob;
    }
}

extern "C" void kernel_launch(void* const* d_in, const int* in_sizes, int n_in,
                              void* d_out, int out_size)
{
    (void)in_sizes; (void)n_in; (void)out_size;
    const float* E_S    = (const float*)d_in[0];
    const float* W      = (const float*)d_in[1];
    const int*   pidx   = (const int*)  d_in[2];
    const float* part_W = (const float*)d_in[3];
    const float* part_b = (const float*)d_in[4];
    const float* v      = (const float*)d_in[5];
    const float* c      = (const float*)d_in[6];
    const float* ln_g   = (const float*)d_in[7];
    const float* ln_b   = (const float*)d_in[8];
    const float* proj_W = (const float*)d_in[9];
    const float* proj_b = (const float*)d_in[10];
    const float* out_g  = (const float*)d_in[11];
    const float* out_b  = (const float*)d_in[12];
    float* out = (float*)d_out;

    cudaFuncSetAttribute(k_gemm, cudaFuncAttributeMaxDynamicSharedMemorySize, GEMM_SMEM);

    k_prep<<<1, 128>>>(v, c, ln_g, ln_b);
    k_wconv<<<512, 256>>>(part_W, proj_W);
    k_seg<<<BT / 2, 256>>>(E_S, W, pidx);
    k_gemm<<<dim3(32, 4), 512, GEMM_SMEM>>>(part_b, 0);
    k_gemm<<<dim3(32, 4), 512, GEMM_SMEM>>>(part_b, 1);
    k_comb<<<BT / 16, 256>>>(proj_b, out_g, out_b, out);
}